// round 1
// baseline (speedup 1.0000x reference)
#include <cuda_runtime.h>
#include <math.h>

// ---------------------------------------------------------------------------
// Problem constants
// ---------------------------------------------------------------------------
#define NB   64     // batch
#define CCH  64     // channels
#define TT   300    // time
#define VV   25     // vertices
#define SS   3      // subsets
#define IC   16     // inter channels
#define TV   (TT*VV)          // 7500
#define KROWS (IC*TT)         // 4800

// Scratch (device globals — no allocation allowed)
__device__ float g_t1[SS * NB * IC * TV];   // 23,040,000 floats
__device__ float g_t2[SS * NB * IC * TV];
__device__ float g_A1[SS * NB * VV * VV];
__device__ float g_Afull[SS * VV * VV];

// ---------------------------------------------------------------------------
// K0: A_full = A + PA + (8A^4 - 4A^2 - 4A + I)   (elementwise powers)
// ---------------------------------------------------------------------------
__global__ void k_afull(const float* __restrict__ A, const float* __restrict__ PA) {
    for (int idx = threadIdx.x; idx < SS * VV * VV; idx += blockDim.x) {
        int r = idx % (VV * VV);
        int v1 = r / VV, v2 = r % VV;
        float a = A[idx];
        float a2 = a * a;
        float ch = 8.f * a2 * a2 - 4.f * a2 - 4.f * a + (v1 == v2 ? 1.f : 0.f);
        g_Afull[idx] = a + PA[idx] + ch;
    }
}

// ---------------------------------------------------------------------------
// K1: t1/t2 = slim_conv(x, WT1/WT2, pad_t=4) for all subsets.
// grid: (10, N, S), block: 416 (400 active = 16 t-pairs x 25 v)
// smem: W1,W2 as [ci][dt][co] float (vectorizable over co), 73728 B dynamic.
// ---------------------------------------------------------------------------
__global__ __launch_bounds__(416, 1)
void k_conv(const float* __restrict__ x,
            const float* __restrict__ WT1, const float* __restrict__ bT1,
            const float* __restrict__ WT2, const float* __restrict__ bT2,
            const float* __restrict__ weights) {
    const int s = blockIdx.z;
    const int n = blockIdx.y;
    extern __shared__ float sw[];
    float* sW1 = sw;            // 9216
    float* sW2 = sw + 9216;     // 9216

    const float* W1g = WT1 + s * IC * CCH * 9;
    const float* W2g = WT2 + s * IC * CCH * 9;
    for (int idx = threadIdx.x; idx < IC * CCH * 9; idx += 416) {
        int ci = idx / 144;
        int r = idx - ci * 144;
        int dt = r >> 4;
        int co = r & 15;
        int gidx = (co * CCH + ci) * 9 + dt;
        sW1[idx] = W1g[gidx];
        sW2[idx] = W2g[gidx];
    }
    __syncthreads();

    const int tid = threadIdx.x;
    if (tid >= 400) return;
    const int tp = tid / 25;
    const int v = tid - tp * 25;
    const int t0 = blockIdx.x * 32 + tp * 2;     // always even
    if (t0 >= TT) return;

    float a10[16], a11[16], a20[16], a21[16];
#pragma unroll
    for (int i = 0; i < 16; i++) { a10[i] = 0.f; a11[i] = 0.f; a20[i] = 0.f; a21[i] = 0.f; }

    const float4* w1f = (const float4*)sW1;
    const float4* w2f = (const float4*)sW2;
    const float* xb = x + n * CCH * TV + v;

    for (int ci = 0; ci < CCH; ci++) {
        const float* xp = xb + ci * TV;
        float xr[10];
#pragma unroll
        for (int k = 0; k < 10; k++) {
            int tt = t0 - 4 + k;
            xr[k] = (tt >= 0 && tt < TT) ? __ldg(xp + tt * VV) : 0.f;
        }
#pragma unroll
        for (int dt = 0; dt < 9; dt++) {
            const float4* wp1 = w1f + (ci * 9 + dt) * 4;
            const float4* wp2 = w2f + (ci * 9 + dt) * 4;
            float x0 = xr[dt], x1 = xr[dt + 1];
#pragma unroll
            for (int q = 0; q < 4; q++) {
                float4 w1v = wp1[q];
                float4 w2v = wp2[q];
                a10[4*q+0] += w1v.x * x0; a10[4*q+1] += w1v.y * x0;
                a10[4*q+2] += w1v.z * x0; a10[4*q+3] += w1v.w * x0;
                a11[4*q+0] += w1v.x * x1; a11[4*q+1] += w1v.y * x1;
                a11[4*q+2] += w1v.z * x1; a11[4*q+3] += w1v.w * x1;
                a20[4*q+0] += w2v.x * x0; a20[4*q+1] += w2v.y * x0;
                a20[4*q+2] += w2v.z * x0; a20[4*q+3] += w2v.w * x0;
                a21[4*q+0] += w2v.x * x1; a21[4*q+1] += w2v.y * x1;
                a21[4*q+2] += w2v.z * x1; a21[4*q+3] += w2v.w * x1;
            }
        }
    }

    const float ws1 = __ldg(weights + 1), ws2 = __ldg(weights + 2);
    const float ws3 = __ldg(weights + 3), ws4 = __ldg(weights + 4);
    const int base = ((s * NB + n) * IC) * TV + t0 * VV + v;
#pragma unroll
    for (int co = 0; co < IC; co++) {
        // slim splits for out_c=16: 9, 11, 12, 14
        float sc = (co < 9) ? 1.f : (co < 11) ? ws1 : (co < 12) ? ws2 : (co < 14) ? ws3 : ws4;
        float b1 = __ldg(bT1 + s * IC + co);
        float b2 = __ldg(bT2 + s * IC + co);
        int o = base + co * TV;
        g_t1[o]      = sc * (a10[co] + b1);
        g_t1[o + VV] = sc * (a11[co] + b1);
        g_t2[o]      = sc * (a20[co] + b2);
        g_t2[o + VV] = sc * (a21[co] + b2);
    }
}

// ---------------------------------------------------------------------------
// K2: attention logits + softmax(axis=-2 i.e. over v1) + A_full -> A1
// grid: (N, S), block 640 (625 active, one (v1,v2) each)
// ---------------------------------------------------------------------------
__global__ __launch_bounds__(640, 2)
void k_att() {
    const int n = blockIdx.x;
    const int s = blockIdx.y;
    __shared__ float s1[64 * VV];
    __shared__ float s2[64 * VV];
    __shared__ float sl[VV * VV];

    const float* t1b = g_t1 + (size_t)(s * NB + n) * IC * TV;
    const float* t2b = g_t2 + (size_t)(s * NB + n) * IC * TV;

    const int tid = threadIdx.x;
    const int v1 = tid / 25;
    const int v2 = tid - v1 * 25;
    const bool act = tid < VV * VV;
    float acc = 0.f;

    for (int ch = 0; ch < KROWS / 64; ch++) {
        for (int idx = tid; idx < 64 * VV; idx += 640) {
            int row = idx / VV, vv = idx - row * VV;
            int cr = ch * 64 + row;
            int c = cr / TT, t = cr - c * TT;
            int off = c * TV + t * VV + vv;
            s1[idx] = t1b[off];
            s2[idx] = t2b[off];
        }
        __syncthreads();
        if (act) {
#pragma unroll 8
            for (int k = 0; k < 64; k++)
                acc += s1[k * VV + v1] * s2[k * VV + v2];
        }
        __syncthreads();
    }

    if (act) sl[tid] = acc * (1.0f / (float)KROWS);
    __syncthreads();

    if (tid < VV) {
        const int c2 = tid;
        float m = -1e30f;
#pragma unroll
        for (int r = 0; r < VV; r++) m = fmaxf(m, sl[r * VV + c2]);
        float sum = 0.f;
#pragma unroll
        for (int r = 0; r < VV; r++) sum += expf(sl[r * VV + c2] - m);
        float inv = 1.f / sum;
        const float* af = g_Afull + s * VV * VV;
        float* a1o = g_A1 + (size_t)(s * NB + n) * VV * VV;
#pragma unroll
        for (int r = 0; r < VV; r++)
            a1o[r * VV + c2] = af[r * VV + c2] + expf(sl[r * VV + c2] - m) * inv;
    }
}

// ---------------------------------------------------------------------------
// K3: for each (n, t-tile of 10):
//   for s: agg = x @ A1[s,n] ; zacc += Wd[s]^T-fold of agg (in registers)
//   out = relu(ka*zacc + kb + x)   (slim scale + biases + BN folded into ka/kb)
// grid: (30, N), block 256 (250 active, one (t,v2) each)
// dyn smem: xs[250][68] + WdT[64][64] + A1s[625] + ka[64] + kb[64] = 87396 B
// ---------------------------------------------------------------------------
#define TT2 10
__global__ __launch_bounds__(256, 2)
void k_aggz(const float* __restrict__ x,
            const float* __restrict__ Wd, const float* __restrict__ bd,
            const float* __restrict__ weights,
            const float* __restrict__ bng, const float* __restrict__ bnb,
            const float* __restrict__ bnm, const float* __restrict__ bnv,
            float* __restrict__ out) {
    extern __shared__ float sm[];
    float* xs  = sm;              // 250*68 = 17000
    float* WdT = xs + 17000;      // 4096
    float* A1s = WdT + 4096;      // 625
    float* ka  = A1s + 625;       // 64
    float* kb  = ka + 64;         // 64

    const int n  = blockIdx.y;
    const int t0 = blockIdx.x * TT2;
    const int tid = threadIdx.x;
    const int nb = n * CCH * TV;

    // stage x tile transposed: xs[(t*25+v)*68 + ci] = x[n][ci][t0+t][v]
    for (int idx = tid; idx < CCH * TT2 * VV; idx += 256) {
        int ci = idx / (TT2 * VV);
        int tv = idx - ci * (TT2 * VV);
        xs[tv * 68 + ci] = x[nb + ci * TV + t0 * VV + tv];
    }
    // stage fused epilogue constants
    if (tid < CCH) {
        int co = tid;
        float ws1 = weights[1], ws2 = weights[2], ws3 = weights[3], ws4 = weights[4];
        // slim splits for out_c=64: 38, 44, 51, 57
        float sc = (co < 38) ? 1.f : (co < 44) ? ws1 : (co < 51) ? ws2 : (co < 57) ? ws3 : ws4;
        float bdsum = bd[co] + bd[CCH + co] + bd[2 * CCH + co];
        float fa = bng[co] * rsqrtf(bnv[co] + 1e-5f);
        ka[co] = fa * sc;
        kb[co] = fa * sc * bdsum + bnb[co] - bnm[co] * fa;
    }

    float zacc[64];
#pragma unroll
    for (int i = 0; i < 64; i++) zacc[i] = 0.f;

    const int tv = tid;
    const bool act = tid < TT2 * VV;
    const int tloc = tv / 25;
    const int v2 = tv - tloc * 25;

    for (int s = 0; s < SS; s++) {
        __syncthreads();   // protect previous WdT/A1s readers
        for (int idx = tid; idx < CCH * CCH; idx += 256) {
            int ci = idx >> 6;
            int co = idx & 63;
            WdT[ci * 64 + co] = Wd[(s * CCH + co) * CCH + ci];
        }
        for (int idx = tid; idx < VV * VV; idx += 256)
            A1s[idx] = g_A1[(size_t)(s * NB + n) * VV * VV + idx];
        __syncthreads();

        if (act) {
#pragma unroll
            for (int cb = 0; cb < 64; cb += 16) {
                float a[16];
#pragma unroll
                for (int i = 0; i < 16; i++) a[i] = 0.f;
#pragma unroll
                for (int vv1 = 0; vv1 < VV; vv1++) {
                    float aw = A1s[vv1 * VV + v2];
                    const float4* xp = (const float4*)(xs + (tloc * 25 + vv1) * 68 + cb);
#pragma unroll
                    for (int q = 0; q < 4; q++) {
                        float4 xv = xp[q];
                        a[4*q+0] += xv.x * aw; a[4*q+1] += xv.y * aw;
                        a[4*q+2] += xv.z * aw; a[4*q+3] += xv.w * aw;
                    }
                }
#pragma unroll
                for (int ci = 0; ci < 16; ci++) {
                    float av = a[ci];
                    const float4* wp = (const float4*)(WdT + (cb + ci) * 64);
#pragma unroll
                    for (int q = 0; q < 16; q++) {
                        float4 wv = wp[q];
                        zacc[4*q+0] += wv.x * av; zacc[4*q+1] += wv.y * av;
                        zacc[4*q+2] += wv.z * av; zacc[4*q+3] += wv.w * av;
                    }
                }
            }
        }
    }

    if (act) {
        const float* xrow = xs + (tloc * 25 + v2) * 68;
        const int ob = nb + t0 * VV + tv;
#pragma unroll
        for (int co = 0; co < CCH; co++) {
            float val = ka[co] * zacc[co] + kb[co] + xrow[co];
            out[ob + co * TV] = fmaxf(val, 0.f);
        }
    }
}

// ---------------------------------------------------------------------------
// launch
// ---------------------------------------------------------------------------
extern "C" void kernel_launch(void* const* d_in, const int* in_sizes, int n_in,
                              void* d_out, int out_size) {
    const float* x    = (const float*)d_in[0];
    const float* wts  = (const float*)d_in[1];
    const float* A    = (const float*)d_in[2];
    const float* PA   = (const float*)d_in[3];
    const float* Wd   = (const float*)d_in[4];
    const float* bd   = (const float*)d_in[5];
    const float* WT1  = (const float*)d_in[6];
    const float* bT1  = (const float*)d_in[7];
    const float* WT2  = (const float*)d_in[8];
    const float* bT2  = (const float*)d_in[9];
    const float* bng  = (const float*)d_in[10];
    const float* bnb  = (const float*)d_in[11];
    const float* bnm  = (const float*)d_in[12];
    const float* bnv  = (const float*)d_in[13];
    float* out = (float*)d_out;

    const int conv_smem = 2 * IC * CCH * 9 * 4;           // 73728
    const int aggz_smem = (17000 + 4096 + 625 + 128) * 4; // 87396
    cudaFuncSetAttribute(k_conv, cudaFuncAttributeMaxDynamicSharedMemorySize, conv_smem);
    cudaFuncSetAttribute(k_aggz, cudaFuncAttributeMaxDynamicSharedMemorySize, aggz_smem);

    k_afull<<<1, 640>>>(A, PA);
    k_conv<<<dim3(10, NB, SS), 416, conv_smem>>>(x, WT1, bT1, WT2, bT2, wts);
    k_att<<<dim3(NB, SS), 640>>>();
    k_aggz<<<dim3(TT / TT2, NB), 256, aggz_smem>>>(x, Wd, bd, wts, bng, bnb, bnm, bnv, out);
}